// round 7
// baseline (speedup 1.0000x reference)
#include <cuda_runtime.h>
#include <cuda_bf16.h>
#include <cstdint>

#define T_SEQ 4096
#define C_EMB 1024
#define NH 8
#define HD 128
#define HALF 64

// Scratch (device globals: allocation-free per harness rules)
__device__ float g_q[T_SEQ * C_EMB];
__device__ float g_k[T_SEQ * C_EMB];
__device__ float g_v[T_SEQ * C_EMB];
__device__ float g_y[T_SEQ * C_EMB];

__device__ __forceinline__ uint32_t f2tf(float x) {
    uint32_t r;
    asm("cvt.rna.tf32.f32 %0, %1;" : "=r"(r) : "f"(x));
    return r;
}

__device__ __forceinline__ uint32_t shfl4(uint32_t v, int src) {
    return __shfl_sync(0xffffffffu, v, src, 4);
}

#define MMA_TF32(ACC, A0, A1, A2, A3, B0, B1)                              \
    asm volatile(                                                          \
        "mma.sync.aligned.m16n8k8.row.col.f32.tf32.tf32.f32 "              \
        "{%0,%1,%2,%3}, {%4,%5,%6,%7}, {%8,%9}, {%0,%1,%2,%3};"            \
        : "+f"((ACC)[0]), "+f"((ACC)[1]), "+f"((ACC)[2]), "+f"((ACC)[3])   \
        : "r"(A0), "r"(A1), "r"(A2), "r"(A3), "r"(B0), "r"(B1))

__device__ __forceinline__ void cp_async16(void* smem, const void* gmem) {
    uint32_t s = (uint32_t)__cvta_generic_to_shared(smem);
    asm volatile("cp.async.ca.shared.global [%0], [%1], 16;" :: "r"(s), "l"(gmem));
}
#define CP_COMMIT() asm volatile("cp.async.commit_group;")
#define CP_WAIT0()  asm volatile("cp.async.wait_group 0;")

// ---------------------------------------------------------------------------
// TF32 tensor-core GEMM, cp.async double-buffered.
// C[M,N] = A[M,K] @ B[K,N], fp32 in/out, tf32 cvt at fragment load.
// BM=BN=128, BK=16, 256 threads = 8 warps, warp tile 64x32.
// blockIdx.z selects (B,C) pair -> q/k/v fused in one launch.
// ---------------------------------------------------------------------------
#define AS_STRIDE 20
#define BS_STRIDE 136

__global__ __launch_bounds__(256) void gemm_tf32_kernel(
    const float* __restrict__ A,
    const float* __restrict__ Bp0, const float* __restrict__ Bp1,
    const float* __restrict__ Bp2,
    float* __restrict__ Cp0, float* __restrict__ Cp1, float* __restrict__ Cp2,
    int M, int N, int K)
{
    const float* B = (blockIdx.z == 0) ? Bp0 : (blockIdx.z == 1 ? Bp1 : Bp2);
    float*       C = (blockIdx.z == 0) ? Cp0 : (blockIdx.z == 1 ? Cp1 : Cp2);

    __shared__ float As[2][128 * AS_STRIDE];
    __shared__ float Bs[2][16 * BS_STRIDE];

    int tid = threadIdx.x;
    int lane = tid & 31, warp = tid >> 5;
    int wm = (warp >> 2) * 64;
    int wn = (warp & 3) * 32;
    int bm = blockIdx.y * 128, bn = blockIdx.x * 128;

    float acc[4][4][4];
    #pragma unroll
    for (int mt = 0; mt < 4; ++mt)
        #pragma unroll
        for (int nt = 0; nt < 4; ++nt)
            #pragma unroll
            for (int i = 0; i < 4; ++i) acc[mt][nt][i] = 0.f;

    auto issue = [&](int it, int buf) {
        int k0 = it * 16;
        #pragma unroll
        for (int j = 0; j < 2; ++j) {
            int i = tid + j * 256;
            int r = i >> 2, c4 = (i & 3) << 2;
            cp_async16(&As[buf][r * AS_STRIDE + c4], &A[(bm + r) * K + k0 + c4]);
        }
        #pragma unroll
        for (int j = 0; j < 2; ++j) {
            int i = tid + j * 256;
            int r = i >> 5, c4 = (i & 31) << 2;
            cp_async16(&Bs[buf][r * BS_STRIDE + c4], &B[(k0 + r) * N + bn + c4]);
        }
        CP_COMMIT();
    };

    const int nIter = K / 16;
    issue(0, 0);
    CP_WAIT0();
    __syncthreads();

    for (int it = 0; it < nIter; ++it) {
        int cur = it & 1;
        if (it + 1 < nIter) issue(it + 1, cur ^ 1);

        const float* Ab = As[cur];
        const float* Bb = Bs[cur];
        #pragma unroll
        for (int ks = 0; ks < 2; ++ks) {
            int kb = ks * 8;
            uint32_t af[4][4];
            #pragma unroll
            for (int mt = 0; mt < 4; ++mt) {
                int r0 = wm + mt * 16 + (lane >> 2);
                int c0 = kb + (lane & 3);
                af[mt][0] = f2tf(Ab[r0 * AS_STRIDE + c0]);
                af[mt][1] = f2tf(Ab[(r0 + 8) * AS_STRIDE + c0]);
                af[mt][2] = f2tf(Ab[r0 * AS_STRIDE + c0 + 4]);
                af[mt][3] = f2tf(Ab[(r0 + 8) * AS_STRIDE + c0 + 4]);
            }
            uint32_t bf[4][2];
            #pragma unroll
            for (int nt = 0; nt < 4; ++nt) {
                int rr = kb + (lane & 3);
                int cc = wn + nt * 8 + (lane >> 2);
                bf[nt][0] = f2tf(Bb[rr * BS_STRIDE + cc]);
                bf[nt][1] = f2tf(Bb[(rr + 4) * BS_STRIDE + cc]);
            }
            #pragma unroll
            for (int mt = 0; mt < 4; ++mt)
                #pragma unroll
                for (int nt = 0; nt < 4; ++nt)
                    MMA_TF32(acc[mt][nt], af[mt][0], af[mt][1], af[mt][2],
                             af[mt][3], bf[nt][0], bf[nt][1]);
        }

        if (it + 1 < nIter) {
            CP_WAIT0();
            __syncthreads();
        }
    }

    #pragma unroll
    for (int mt = 0; mt < 4; ++mt) {
        int row = bm + wm + mt * 16 + (lane >> 2);
        #pragma unroll
        for (int nt = 0; nt < 4; ++nt) {
            int col = bn + wn + nt * 8 + ((lane & 3) << 1);
            *(float2*)&C[row * N + col] =
                make_float2(acc[mt][nt][0], acc[mt][nt][1]);
            *(float2*)&C[(row + 8) * N + col] =
                make_float2(acc[mt][nt][2], acc[mt][nt][3]);
        }
    }
}

// ---------------------------------------------------------------------------
// v += 2*sigmoid(x[:, :32] @ w_gate)[h] * ve     (one block per token)
// ---------------------------------------------------------------------------
__global__ __launch_bounds__(256) void gate_ve_kernel(
    const float* __restrict__ x, const float* __restrict__ ve,
    const float* __restrict__ w_gate)
{
    int t = blockIdx.x;
    __shared__ float xs[32];
    __shared__ float gate[NH];
    int tid = threadIdx.x;
    if (tid < 32) xs[tid] = x[t * C_EMB + tid];
    __syncthreads();
    if (tid < NH) {
        float s = 0.f;
        #pragma unroll
        for (int c = 0; c < 32; ++c) s += xs[c] * w_gate[c * NH + tid];
        gate[tid] = 2.f / (1.f + __expf(-s));
    }
    __syncthreads();
    for (int i = tid; i < C_EMB; i += 256)
        g_v[t * C_EMB + i] += gate[i >> 7] * ve[t * C_EMB + i];
}

// ---------------------------------------------------------------------------
// RoPE + RMSnorm on q (z=0) and k (z=1). One 64-thread block per (token, head).
// ---------------------------------------------------------------------------
__global__ __launch_bounds__(64) void rope_norm_kernel(
    const float* __restrict__ cosb, const float* __restrict__ sinb)
{
    float* buf = (blockIdx.z == 0) ? g_q : g_k;
    int t = blockIdx.x, h = blockIdx.y;
    int d = threadIdx.x;
    float* p = buf + t * C_EMB + h * HD;

    float x1 = p[d], x2 = p[d + HALF];
    float cs = cosb[t * HALF + d], sn = sinb[t * HALF + d];
    float y1 = x1 * cs + x2 * sn;
    float y2 = -x1 * sn + x2 * cs;

    float ss = y1 * y1 + y2 * y2;
    #pragma unroll
    for (int o = 16; o; o >>= 1) ss += __shfl_xor_sync(0xffffffffu, ss, o);
    __shared__ float w2[2];
    if ((d & 31) == 0) w2[d >> 5] = ss;
    __syncthreads();
    float tot = w2[0] + w2[1];
    float r = rsqrtf(tot * (1.f / HD) + 1e-6f);
    p[d] = y1 * r;
    p[d + HALF] = y2 * r;
}

// ---------------------------------------------------------------------------
// Tensor-core windowed flash attention v2 (TF32 MMA, fp32 accum).
// Block = 128 queries x 1 head, 256 threads / 8 warps (warp = 16 q rows).
// Software pipeline: raw K/V prefetched to REGISTERS during compute of the
// previous tile, cvt(rna)+STS to double-buffered tf32 smem at tile start.
// ONE __syncthreads per tile. P kept in registers: C-frag -> A-frag layout
// conversion via width-4 shuffles (no P smem, no syncwarp).
// ---------------------------------------------------------------------------
#define BQ 128
#define BK 64
#define QS2 132
#define KS2 132
#define VS2 136
#define ATTN_SMEM ((BQ * QS2 + 2 * BK * KS2 + 2 * BK * VS2) * 4)  // 200 KB

__global__ __launch_bounds__(256) void attn_mma_kernel(const int* __restrict__ winp)
{
    extern __shared__ uint32_t smw[];
    uint32_t* Qs  = smw;                     // 128 x 132 tf32
    uint32_t* Ks0 = Qs + BQ * QS2;           // 2 x (64 x 132) tf32
    uint32_t* Vs0 = Ks0 + 2 * BK * KS2;      // 2 x (64 x 136) tf32

    int W = *winp;
    int q0 = blockIdx.x * BQ;
    int h  = blockIdx.y;
    int tid = threadIdx.x, lane = tid & 31, warp = tid >> 5;
    int wm = warp * 16;
    int qr = lane >> 2, qc = lane & 3;
    const float scale = 0.08838834764831845f; // 1/sqrt(128)

    // Q tile -> smem (tf32)
    for (int i = tid; i < BQ * 32; i += 256) {
        int r = i >> 5, c4 = (i & 31) << 2;
        float4 v = *(const float4*)&g_q[(q0 + r) * C_EMB + h * HD + c4];
        *(uint4*)&Qs[r * QS2 + c4] =
            make_uint4(f2tf(v.x), f2tf(v.y), f2tf(v.z), f2tf(v.w));
    }

    float O[16][4];
    #pragma unroll
    for (int nt = 0; nt < 16; ++nt)
        #pragma unroll
        for (int i = 0; i < 4; ++i) O[nt][i] = 0.f;
    float m1 = -1e30f, m2 = -1e30f, l1 = 0.f, l2 = 0.f;

    int r1 = q0 + wm + qr, r2 = r1 + 8;

    int lo = q0 - W + 1; if (lo < 0) lo = 0;
    int kt0 = lo >> 6;
    int kt1 = (q0 + BQ - 1) >> 6;

    // Prefetch first K/V tile into registers (raw fp32).
    int pr = tid >> 5, pc4 = (tid & 31) << 2;
    float4 rk[8], rv[8];
    {
        int kb = kt0 * BK;
        #pragma unroll
        for (int j = 0; j < 8; ++j) {
            int row = (kb + pr + j * 8) * C_EMB + h * HD + pc4;
            rk[j] = *(const float4*)&g_k[row];
            rv[j] = *(const float4*)&g_v[row];
        }
    }

    for (int kt = kt0; kt <= kt1; ++kt) {
        int buf = kt & 1;
        uint32_t* Ks = Ks0 + buf * (BK * KS2);
        uint32_t* Vs = Vs0 + buf * (BK * VS2);

        // Stage registers -> smem (cvt rna to tf32)
        #pragma unroll
        for (int j = 0; j < 8; ++j) {
            int r = pr + j * 8;
            *(uint4*)&Ks[r * KS2 + pc4] =
                make_uint4(f2tf(rk[j].x), f2tf(rk[j].y), f2tf(rk[j].z), f2tf(rk[j].w));
            *(uint4*)&Vs[r * VS2 + pc4] =
                make_uint4(f2tf(rv[j].x), f2tf(rv[j].y), f2tf(rv[j].z), f2tf(rv[j].w));
        }
        __syncthreads();   // the only barrier per tile

        // Prefetch next tile (latency hidden by compute below)
        if (kt < kt1) {
            int nb = (kt + 1) * BK;
            #pragma unroll
            for (int j = 0; j < 8; ++j) {
                int row = (nb + pr + j * 8) * C_EMB + h * HD + pc4;
                rk[j] = *(const float4*)&g_k[row];
                rv[j] = *(const float4*)&g_v[row];
            }
        }

        int kbase = kt * BK;

        // S = Q @ K^T
        float sc[8][4];
        #pragma unroll
        for (int nt = 0; nt < 8; ++nt)
            #pragma unroll
            for (int i = 0; i < 4; ++i) sc[nt][i] = 0.f;

        #pragma unroll
        for (int ks = 0; ks < 16; ++ks) {
            int ab = (wm + qr) * QS2 + ks * 8 + qc;
            uint32_t a0 = Qs[ab], a1 = Qs[ab + 8 * QS2];
            uint32_t a2 = Qs[ab + 4], a3 = Qs[ab + 8 * QS2 + 4];
            #pragma unroll
            for (int nt = 0; nt < 8; ++nt) {
                int bb = (nt * 8 + qr) * KS2 + ks * 8 + qc;
                MMA_TF32(sc[nt], a0, a1, a2, a3, Ks[bb], Ks[bb + 4]);
            }
        }

        // Mask + scale + row max
        float mx1 = -1e30f, mx2 = -1e30f;
        #pragma unroll
        for (int nt = 0; nt < 8; ++nt) {
            int c0 = kbase + nt * 8 + qc * 2;
            int c1 = c0 + 1;
            sc[nt][0] = ((c0 <= r1) && (r1 - c0 < W)) ? sc[nt][0] * scale : -1e30f;
            sc[nt][1] = ((c1 <= r1) && (r1 - c1 < W)) ? sc[nt][1] * scale : -1e30f;
            sc[nt][2] = ((c0 <= r2) && (r2 - c0 < W)) ? sc[nt][2] * scale : -1e30f;
            sc[nt][3] = ((c1 <= r2) && (r2 - c1 < W)) ? sc[nt][3] * scale : -1e30f;
            mx1 = fmaxf(mx1, fmaxf(sc[nt][0], sc[nt][1]));
            mx2 = fmaxf(mx2, fmaxf(sc[nt][2], sc[nt][3]));
        }
        mx1 = fmaxf(mx1, __shfl_xor_sync(0xffffffffu, mx1, 1));
        mx1 = fmaxf(mx1, __shfl_xor_sync(0xffffffffu, mx1, 2));
        mx2 = fmaxf(mx2, __shfl_xor_sync(0xffffffffu, mx2, 1));
        mx2 = fmaxf(mx2, __shfl_xor_sync(0xffffffffu, mx2, 2));

        float mn1 = fmaxf(m1, mx1), mn2 = fmaxf(m2, mx2);
        float al1 = __expf(m1 - mn1), al2 = __expf(m2 - mn2);
        m1 = mn1; m2 = mn2;

        // exp -> register P (tf32 bits)
        uint32_t up[8][4];
        float ls1 = 0.f, ls2 = 0.f;
        #pragma unroll
        for (int nt = 0; nt < 8; ++nt) {
            float p0 = __expf(sc[nt][0] - mn1);
            float p1 = __expf(sc[nt][1] - mn1);
            float p2 = __expf(sc[nt][2] - mn2);
            float p3 = __expf(sc[nt][3] - mn2);
            ls1 += p0 + p1;
            ls2 += p2 + p3;
            up[nt][0] = f2tf(p0); up[nt][1] = f2tf(p1);
            up[nt][2] = f2tf(p2); up[nt][3] = f2tf(p3);
        }
        ls1 += __shfl_xor_sync(0xffffffffu, ls1, 1);
        ls1 += __shfl_xor_sync(0xffffffffu, ls1, 2);
        ls2 += __shfl_xor_sync(0xffffffffu, ls2, 1);
        ls2 += __shfl_xor_sync(0xffffffffu, ls2, 2);
        l1 = l1 * al1 + ls1;
        l2 = l2 * al2 + ls2;

        #pragma unroll
        for (int nt = 0; nt < 16; ++nt) {
            O[nt][0] *= al1; O[nt][1] *= al1;
            O[nt][2] *= al2; O[nt][3] *= al2;
        }

        // O += P @ V with register P (quad-shuffle C-frag -> A-frag transpose)
        int src = qc >> 1;
        bool odd = qc & 1;
        #pragma unroll
        for (int ks = 0; ks < 8; ++ks) {
            uint32_t x0 = shfl4(up[ks][0], src),     x1 = shfl4(up[ks][1], src);
            uint32_t x2 = shfl4(up[ks][2], src),     x3 = shfl4(up[ks][3], src);
            uint32_t y0 = shfl4(up[ks][0], src + 2), y1 = shfl4(up[ks][1], src + 2);
            uint32_t y2 = shfl4(up[ks][2], src + 2), y3 = shfl4(up[ks][3], src + 2);
            uint32_t a0 = odd ? x1 : x0, a1 = odd ? x3 : x2;
            uint32_t a2 = odd ? y1 : y0, a3 = odd ? y3 : y2;
            #pragma unroll
            for (int nt = 0; nt < 16; ++nt) {
                int vb = (ks * 8 + qc) * VS2 + nt * 8 + qr;
                MMA_TF32(O[nt], a0, a1, a2, a3, Vs[vb], Vs[vb + 4 * VS2]);
            }
        }
        // no trailing barrier: next iter writes the OTHER buffer, and its
        // single barrier proves all warps left the iteration before that.
    }

    float inv1 = 1.f / l1, inv2 = 1.f / l2;
    #pragma unroll
    for (int nt = 0; nt < 16; ++nt) {
        int col = h * HD + nt * 8 + qc * 2;
        *(float2*)&g_y[r1 * C_EMB + col] =
            make_float2(O[nt][0] * inv1, O[nt][1] * inv1);
        *(float2*)&g_y[r2 * C_EMB + col] =
            make_float2(O[nt][2] * inv2, O[nt][3] * inv2);
    }
}

// ---------------------------------------------------------------------------
extern "C" void kernel_launch(void* const* d_in, const int* in_sizes, int n_in,
                              void* d_out, int out_size)
{
    const float* x    = (const float*)d_in[0];
    const float* ve   = (const float*)d_in[1];
    const float* cosb = (const float*)d_in[2];
    const float* sinb = (const float*)d_in[3];
    const float* wq   = (const float*)d_in[4];
    const float* wk   = (const float*)d_in[5];
    const float* wv   = (const float*)d_in[6];
    const float* wg   = (const float*)d_in[7];
    const float* wp   = (const float*)d_in[8];
    const int*   win  = (const int*)d_in[9];
    float* out = (float*)d_out;

    float *q, *k, *v, *y;
    cudaGetSymbolAddress((void**)&q, g_q);
    cudaGetSymbolAddress((void**)&k, g_k);
    cudaGetSymbolAddress((void**)&v, g_v);
    cudaGetSymbolAddress((void**)&y, g_y);

    // Fused q/k/v projections: one launch, blockIdx.z picks weight/output.
    dim3 gqkv(C_EMB / 128, T_SEQ / 128, 3);
    gemm_tf32_kernel<<<gqkv, 256>>>(x, wq, wk, wv, q, k, v,
                                    T_SEQ, C_EMB, C_EMB);

    gate_ve_kernel<<<T_SEQ, 256>>>(x, ve, wg);
    rope_norm_kernel<<<dim3(T_SEQ, NH, 2), 64>>>(cosb, sinb);

    cudaFuncSetAttribute(attn_mma_kernel,
                         cudaFuncAttributeMaxDynamicSharedMemorySize, ATTN_SMEM);
    attn_mma_kernel<<<dim3(T_SEQ / BQ, NH), 256, ATTN_SMEM>>>(win);

    dim3 gp(C_EMB / 128, T_SEQ / 128, 1);
    gemm_tf32_kernel<<<gp, 256>>>(y, wp, wp, wp, out, out, out,
                                  T_SEQ, C_EMB, C_EMB);
}

// round 16
// speedup vs baseline: 1.4701x; 1.4701x over previous
#include <cuda_runtime.h>
#include <cuda_bf16.h>
#include <cstdint>

#define T_SEQ 4096
#define C_EMB 1024
#define NH 8
#define HD 128
#define HALF 64

// Scratch (device globals: allocation-free per harness rules)
__device__ float g_q[T_SEQ * C_EMB];
__device__ float g_k[T_SEQ * C_EMB];
__device__ float g_v[T_SEQ * C_EMB];
__device__ float g_y[T_SEQ * C_EMB];

__device__ __forceinline__ uint32_t f2tf(float x) {
    uint32_t r;
    asm("cvt.rna.tf32.f32 %0, %1;" : "=r"(r) : "f"(x));
    return r;
}

__device__ __forceinline__ uint32_t shfl4(uint32_t v, int src) {
    return __shfl_sync(0xffffffffu, v, src, 4);
}

#define MMA_TF32(ACC, A0, A1, A2, A3, B0, B1)                              \
    asm volatile(                                                          \
        "mma.sync.aligned.m16n8k8.row.col.f32.tf32.tf32.f32 "              \
        "{%0,%1,%2,%3}, {%4,%5,%6,%7}, {%8,%9}, {%0,%1,%2,%3};"            \
        : "+f"((ACC)[0]), "+f"((ACC)[1]), "+f"((ACC)[2]), "+f"((ACC)[3])   \
        : "r"(A0), "r"(A1), "r"(A2), "r"(A3), "r"(B0), "r"(B1))

__device__ __forceinline__ void cp_async16(void* smem, const void* gmem) {
    uint32_t s = (uint32_t)__cvta_generic_to_shared(smem);
    asm volatile("cp.async.ca.shared.global [%0], [%1], 16;" :: "r"(s), "l"(gmem));
}
#define CP_COMMIT() asm volatile("cp.async.commit_group;")
#define CP_WAIT0()  asm volatile("cp.async.wait_group 0;")

// ---------------------------------------------------------------------------
// TF32 tensor-core GEMM, cp.async double-buffered (unchanged from R5 best).
// BM=BN=128, BK=16, 256 threads = 8 warps, warp tile 64x32.
// blockIdx.z selects (B,C) pair -> q/k/v fused in one launch.
// ---------------------------------------------------------------------------
#define AS_STRIDE 20
#define BS_STRIDE 136

__global__ __launch_bounds__(256) void gemm_tf32_kernel(
    const float* __restrict__ A,
    const float* __restrict__ Bp0, const float* __restrict__ Bp1,
    const float* __restrict__ Bp2,
    float* __restrict__ Cp0, float* __restrict__ Cp1, float* __restrict__ Cp2,
    int M, int N, int K)
{
    const float* B = (blockIdx.z == 0) ? Bp0 : (blockIdx.z == 1 ? Bp1 : Bp2);
    float*       C = (blockIdx.z == 0) ? Cp0 : (blockIdx.z == 1 ? Cp1 : Cp2);

    __shared__ float As[2][128 * AS_STRIDE];
    __shared__ float Bs[2][16 * BS_STRIDE];

    int tid = threadIdx.x;
    int lane = tid & 31, warp = tid >> 5;
    int wm = (warp >> 2) * 64;
    int wn = (warp & 3) * 32;
    int bm = blockIdx.y * 128, bn = blockIdx.x * 128;

    float acc[4][4][4];
    #pragma unroll
    for (int mt = 0; mt < 4; ++mt)
        #pragma unroll
        for (int nt = 0; nt < 4; ++nt)
            #pragma unroll
            for (int i = 0; i < 4; ++i) acc[mt][nt][i] = 0.f;

    auto issue = [&](int it, int buf) {
        int k0 = it * 16;
        #pragma unroll
        for (int j = 0; j < 2; ++j) {
            int i = tid + j * 256;
            int r = i >> 2, c4 = (i & 3) << 2;
            cp_async16(&As[buf][r * AS_STRIDE + c4], &A[(bm + r) * K + k0 + c4]);
        }
        #pragma unroll
        for (int j = 0; j < 2; ++j) {
            int i = tid + j * 256;
            int r = i >> 5, c4 = (i & 31) << 2;
            cp_async16(&Bs[buf][r * BS_STRIDE + c4], &B[(k0 + r) * N + bn + c4]);
        }
        CP_COMMIT();
    };

    const int nIter = K / 16;
    issue(0, 0);
    CP_WAIT0();
    __syncthreads();

    for (int it = 0; it < nIter; ++it) {
        int cur = it & 1;
        if (it + 1 < nIter) issue(it + 1, cur ^ 1);

        const float* Ab = As[cur];
        const float* Bb = Bs[cur];
        #pragma unroll
        for (int ks = 0; ks < 2; ++ks) {
            int kb = ks * 8;
            uint32_t af[4][4];
            #pragma unroll
            for (int mt = 0; mt < 4; ++mt) {
                int r0 = wm + mt * 16 + (lane >> 2);
                int c0 = kb + (lane & 3);
                af[mt][0] = f2tf(Ab[r0 * AS_STRIDE + c0]);
                af[mt][1] = f2tf(Ab[(r0 + 8) * AS_STRIDE + c0]);
                af[mt][2] = f2tf(Ab[r0 * AS_STRIDE + c0 + 4]);
                af[mt][3] = f2tf(Ab[(r0 + 8) * AS_STRIDE + c0 + 4]);
            }
            uint32_t bf[4][2];
            #pragma unroll
            for (int nt = 0; nt < 4; ++nt) {
                int rr = kb + (lane & 3);
                int cc = wn + nt * 8 + (lane >> 2);
                bf[nt][0] = f2tf(Bb[rr * BS_STRIDE + cc]);
                bf[nt][1] = f2tf(Bb[(rr + 4) * BS_STRIDE + cc]);
            }
            #pragma unroll
            for (int mt = 0; mt < 4; ++mt)
                #pragma unroll
                for (int nt = 0; nt < 4; ++nt)
                    MMA_TF32(acc[mt][nt], af[mt][0], af[mt][1], af[mt][2],
                             af[mt][3], bf[nt][0], bf[nt][1]);
        }

        if (it + 1 < nIter) {
            CP_WAIT0();
            __syncthreads();
        }
    }

    #pragma unroll
    for (int mt = 0; mt < 4; ++mt) {
        int row = bm + wm + mt * 16 + (lane >> 2);
        #pragma unroll
        for (int nt = 0; nt < 4; ++nt) {
            int col = bn + wn + nt * 8 + ((lane & 3) << 1);
            *(float2*)&C[row * N + col] =
                make_float2(acc[mt][nt][0], acc[mt][nt][1]);
            *(float2*)&C[(row + 8) * N + col] =
                make_float2(acc[mt][nt][2], acc[mt][nt][3]);
        }
    }
}

// ---------------------------------------------------------------------------
// v += 2*sigmoid(x[:, :32] @ w_gate)[h] * ve     (one block per token)
// ---------------------------------------------------------------------------
__global__ __launch_bounds__(256) void gate_ve_kernel(
    const float* __restrict__ x, const float* __restrict__ ve,
    const float* __restrict__ w_gate)
{
    int t = blockIdx.x;
    __shared__ float xs[32];
    __shared__ float gate[NH];
    int tid = threadIdx.x;
    if (tid < 32) xs[tid] = x[t * C_EMB + tid];
    __syncthreads();
    if (tid < NH) {
        float s = 0.f;
        #pragma unroll
        for (int c = 0; c < 32; ++c) s += xs[c] * w_gate[c * NH + tid];
        gate[tid] = 2.f / (1.f + __expf(-s));
    }
    __syncthreads();
    for (int i = tid; i < C_EMB; i += 256)
        g_v[t * C_EMB + i] += gate[i >> 7] * ve[t * C_EMB + i];
}

// ---------------------------------------------------------------------------
// RoPE + RMSnorm on q (z=0) and k (z=1). One 64-thread block per (token, head).
// ---------------------------------------------------------------------------
__global__ __launch_bounds__(64) void rope_norm_kernel(
    const float* __restrict__ cosb, const float* __restrict__ sinb)
{
    float* buf = (blockIdx.z == 0) ? g_q : g_k;
    int t = blockIdx.x, h = blockIdx.y;
    int d = threadIdx.x;
    float* p = buf + t * C_EMB + h * HD;

    float x1 = p[d], x2 = p[d + HALF];
    float cs = cosb[t * HALF + d], sn = sinb[t * HALF + d];
    float y1 = x1 * cs + x2 * sn;
    float y2 = -x1 * sn + x2 * cs;

    float ss = y1 * y1 + y2 * y2;
    #pragma unroll
    for (int o = 16; o; o >>= 1) ss += __shfl_xor_sync(0xffffffffu, ss, o);
    __shared__ float w2[2];
    if ((d & 31) == 0) w2[d >> 5] = ss;
    __syncthreads();
    float tot = w2[0] + w2[1];
    float r = rsqrtf(tot * (1.f / HD) + 1e-6f);
    p[d] = y1 * r;
    p[d + HALF] = y2 * r;
}

// ---------------------------------------------------------------------------
// Tensor-core windowed flash attention v3 (TF32 MMA, fp32 accum).
// Block = 64 queries x 1 head, 128 threads / 4 warps (warp = 16 q rows).
// Smem = Q/K/V only (99 KB) -> 2 CTAs/SM: cross-CTA overlap hides load
// latency and barrier stalls. P stays in registers via the quad-shuffle
// C-frag -> A-frag transpose (validated bit-exact in R7).
// All strides 132 (=4 mod 32): every fragment pattern conflict-free.
// ---------------------------------------------------------------------------
#define BQ 64
#define BK 64
#define TS 132
#define ATTN_SMEM (3 * BK * TS * 4)   // 99 KB

__global__ __launch_bounds__(128, 2) void attn_mma_kernel(const int* __restrict__ winp)
{
    extern __shared__ uint32_t smw[];
    uint32_t* Qs = smw;                 // 64 x 132 tf32
    uint32_t* Ks = Qs + BQ * TS;        // 64 x 132 tf32
    uint32_t* Vs = Ks + BK * TS;        // 64 x 132 tf32

    int W = *winp;
    int q0 = blockIdx.x * BQ;
    int h  = blockIdx.y;
    int tid = threadIdx.x, lane = tid & 31, warp = tid >> 5;
    int wm = warp * 16;
    int qr = lane >> 2, qc = lane & 3;
    const float scale = 0.08838834764831845f; // 1/sqrt(128)

    // Q tile -> smem (tf32)
    for (int i = tid; i < BQ * 32; i += 128) {
        int r = i >> 5, c4 = (i & 31) << 2;
        float4 v = *(const float4*)&g_q[(q0 + r) * C_EMB + h * HD + c4];
        *(uint4*)&Qs[r * TS + c4] =
            make_uint4(f2tf(v.x), f2tf(v.y), f2tf(v.z), f2tf(v.w));
    }

    float O[16][4];
    #pragma unroll
    for (int nt = 0; nt < 16; ++nt)
        #pragma unroll
        for (int i = 0; i < 4; ++i) O[nt][i] = 0.f;
    float m1 = -1e30f, m2 = -1e30f, l1 = 0.f, l2 = 0.f;

    int r1 = q0 + wm + qr, r2 = r1 + 8;

    int lo = q0 - W + 1; if (lo < 0) lo = 0;
    int kt0 = lo >> 6;
    int kt1 = (q0 + BQ - 1) >> 6;

    for (int kt = kt0; kt <= kt1; ++kt) {
        int kbase = kt * BK;

        // K/V tiles -> smem (tf32)
        for (int i = tid; i < BK * 32; i += 128) {
            int r = i >> 5, c4 = (i & 31) << 2;
            float4 kv = *(const float4*)&g_k[(kbase + r) * C_EMB + h * HD + c4];
            float4 vv = *(const float4*)&g_v[(kbase + r) * C_EMB + h * HD + c4];
            *(uint4*)&Ks[r * TS + c4] =
                make_uint4(f2tf(kv.x), f2tf(kv.y), f2tf(kv.z), f2tf(kv.w));
            *(uint4*)&Vs[r * TS + c4] =
                make_uint4(f2tf(vv.x), f2tf(vv.y), f2tf(vv.z), f2tf(vv.w));
        }
        __syncthreads();

        // S = Q @ K^T
        float sc[8][4];
        #pragma unroll
        for (int nt = 0; nt < 8; ++nt)
            #pragma unroll
            for (int i = 0; i < 4; ++i) sc[nt][i] = 0.f;

        #pragma unroll
        for (int ks = 0; ks < 16; ++ks) {
            int ab = (wm + qr) * TS + ks * 8 + qc;
            uint32_t a0 = Qs[ab], a1 = Qs[ab + 8 * TS];
            uint32_t a2 = Qs[ab + 4], a3 = Qs[ab + 8 * TS + 4];
            #pragma unroll
            for (int nt = 0; nt < 8; ++nt) {
                int bb = (nt * 8 + qr) * TS + ks * 8 + qc;
                MMA_TF32(sc[nt], a0, a1, a2, a3, Ks[bb], Ks[bb + 4]);
            }
        }

        // Mask + scale + row max
        float mx1 = -1e30f, mx2 = -1e30f;
        #pragma unroll
        for (int nt = 0; nt < 8; ++nt) {
            int c0 = kbase + nt * 8 + qc * 2;
            int c1 = c0 + 1;
            sc[nt][0] = ((c0 <= r1) && (r1 - c0 < W)) ? sc[nt][0] * scale : -1e30f;
            sc[nt][1] = ((c1 <= r1) && (r1 - c1 < W)) ? sc[nt][1] * scale : -1e30f;
            sc[nt][2] = ((c0 <= r2) && (r2 - c0 < W)) ? sc[nt][2] * scale : -1e30f;
            sc[nt][3] = ((c1 <= r2) && (r2 - c1 < W)) ? sc[nt][3] * scale : -1e30f;
            mx1 = fmaxf(mx1, fmaxf(sc[nt][0], sc[nt][1]));
            mx2 = fmaxf(mx2, fmaxf(sc[nt][2], sc[nt][3]));
        }
        mx1 = fmaxf(mx1, __shfl_xor_sync(0xffffffffu, mx1, 1));
        mx1 = fmaxf(mx1, __shfl_xor_sync(0xffffffffu, mx1, 2));
        mx2 = fmaxf(mx2, __shfl_xor_sync(0xffffffffu, mx2, 1));
        mx2 = fmaxf(mx2, __shfl_xor_sync(0xffffffffu, mx2, 2));

        float mn1 = fmaxf(m1, mx1), mn2 = fmaxf(m2, mx2);
        float al1 = __expf(m1 - mn1), al2 = __expf(m2 - mn2);
        m1 = mn1; m2 = mn2;

        // exp -> register P (tf32 bits)
        uint32_t up[8][4];
        float ls1 = 0.f, ls2 = 0.f;
        #pragma unroll
        for (int nt = 0; nt < 8; ++nt) {
            float p0 = __expf(sc[nt][0] - mn1);
            float p1 = __expf(sc[nt][1] - mn1);
            float p2 = __expf(sc[nt][2] - mn2);
            float p3 = __expf(sc[nt][3] - mn2);
            ls1 += p0 + p1;
            ls2 += p2 + p3;
            up[nt][0] = f2tf(p0); up[nt][1] = f2tf(p1);
            up[nt][2] = f2tf(p2); up[nt][3] = f2tf(p3);
        }
        ls1 += __shfl_xor_sync(0xffffffffu, ls1, 1);
        ls1 += __shfl_xor_sync(0xffffffffu, ls1, 2);
        ls2 += __shfl_xor_sync(0xffffffffu, ls2, 1);
        ls2 += __shfl_xor_sync(0xffffffffu, ls2, 2);
        l1 = l1 * al1 + ls1;
        l2 = l2 * al2 + ls2;

        #pragma unroll
        for (int nt = 0; nt < 16; ++nt) {
            O[nt][0] *= al1; O[nt][1] *= al1;
            O[nt][2] *= al2; O[nt][3] *= al2;
        }

        // O += P @ V with register P (quad-shuffle C-frag -> A-frag transpose)
        int src = qc >> 1;
        bool odd = qc & 1;
        #pragma unroll
        for (int ks = 0; ks < 8; ++ks) {
            uint32_t x0 = shfl4(up[ks][0], src),     x1 = shfl4(up[ks][1], src);
            uint32_t x2 = shfl4(up[ks][2], src),     x3 = shfl4(up[ks][3], src);
            uint32_t y0 = shfl4(up[ks][0], src + 2), y1 = shfl4(up[ks][1], src + 2);
            uint32_t y2 = shfl4(up[ks][2], src + 2), y3 = shfl4(up[ks][3], src + 2);
            uint32_t a0 = odd ? x1 : x0, a1 = odd ? x3 : x2;
            uint32_t a2 = odd ? y1 : y0, a3 = odd ? y3 : y2;
            #pragma unroll
            for (int nt = 0; nt < 16; ++nt) {
                int vb = (ks * 8 + qc) * TS + nt * 8 + qr;
                MMA_TF32(O[nt], a0, a1, a2, a3, Vs[vb], Vs[vb + 4 * TS]);
            }
        }
        __syncthreads();   // before next tile overwrites Ks/Vs
    }

    float inv1 = 1.f / l1, inv2 = 1.f / l2;
    #pragma unroll
    for (int nt = 0; nt < 16; ++nt) {
        int col = h * HD + nt * 8 + qc * 2;
        *(float2*)&g_y[r1 * C_EMB + col] =
            make_float2(O[nt][0] * inv1, O[nt][1] * inv1);
        *(float2*)&g_y[r2 * C_EMB + col] =
            make_float2(O[nt][2] * inv2, O[nt][3] * inv2);
    }
}

// ---------------------------------------------------------------------------
extern "C" void kernel_launch(void* const* d_in, const int* in_sizes, int n_in,
                              void* d_out, int out_size)
{
    const float* x    = (const float*)d_in[0];
    const float* ve   = (const float*)d_in[1];
    const float* cosb = (const float*)d_in[2];
    const float* sinb = (const float*)d_in[3];
    const float* wq   = (const float*)d_in[4];
    const float* wk   = (const float*)d_in[5];
    const float* wv   = (const float*)d_in[6];
    const float* wg   = (const float*)d_in[7];
    const float* wp   = (const float*)d_in[8];
    const int*   win  = (const int*)d_in[9];
    float* out = (float*)d_out;

    float *q, *k, *v, *y;
    cudaGetSymbolAddress((void**)&q, g_q);
    cudaGetSymbolAddress((void**)&k, g_k);
    cudaGetSymbolAddress((void**)&v, g_v);
    cudaGetSymbolAddress((void**)&y, g_y);

    // Fused q/k/v projections: one launch, blockIdx.z picks weight/output.
    dim3 gqkv(C_EMB / 128, T_SEQ / 128, 3);
    gemm_tf32_kernel<<<gqkv, 256>>>(x, wq, wk, wv, q, k, v,
                                    T_SEQ, C_EMB, C_EMB);

    gate_ve_kernel<<<T_SEQ, 256>>>(x, ve, wg);
    rope_norm_kernel<<<dim3(T_SEQ, NH, 2), 64>>>(cosb, sinb);

    cudaFuncSetAttribute(attn_mma_kernel,
                         cudaFuncAttributeMaxDynamicSharedMemorySize, ATTN_SMEM);
    attn_mma_kernel<<<dim3(T_SEQ / BQ, NH), 128, ATTN_SMEM>>>(win);

    dim3 gp(C_EMB / 128, T_SEQ / 128, 1);
    gemm_tf32_kernel<<<gp, 256>>>(y, wp, wp, wp, out, out, out,
                                  T_SEQ, C_EMB, C_EMB);
}